// round 10
// baseline (speedup 1.0000x reference)
#include <cuda_runtime.h>
#include <cfloat>

#define HN      488
#define HH      (HN*HN)          // 238144
#define HH4     (HH/4)           // 59536
#define AW      484              // H - RECLEN + 1
#define KK      6
#define NB      32
#define NITERS  10
#define RADIUS  2
#define BAND    22               // 22 bands x 22 rows = 484
#define BW      8192             // uint32 words per batch (2^18 bits)
#define THRESH  0.90f
#define NTH     768

// Scratch (device globals: zero-initialized; bloom cleared by sample's tail)
__device__ float    g_agg[NB*AW*AW];     // 5x5 box means, 30MB (L2-resident)
__device__ float    g_rowmax[NB*AW];
__device__ int      g_rowcol[NB*AW];
__device__ unsigned g_seen[NB*BW];
__device__ unsigned g_dup [NB*BW];

__device__ __forceinline__ unsigned bhash(float v) {
    return (__float_as_uint(v) * 2654435761u) >> 14;   // 18-bit hash
}

// Windows held in registers (fully unrolled; wr/wc stay in regs)
__device__ __forceinline__ bool in_wins_reg(int ii, int jj,
                                            const int (&wr)[KK], const int (&wc)[KK], int nw) {
    bool hit = false;
    #pragma unroll
    for (int s = 0; s < KK; s++)
        if (s < nw && ii >= wr[s] && ii < wr[s]+5 && jj >= wc[s] && jj < wc[s]+5) hit = true;
    return hit;
}

// ---------------------------------------------------------------------------
// Kernel A: box-mean map (stored) + per-row argmax + thresholded dup bloom.
// grid (32 batches, 22 bands), 512 threads.
// ---------------------------------------------------------------------------
__global__ __launch_bounds__(512) void fde_build(const float* __restrict__ hm_in) {
    const int b = blockIdx.x, s = blockIdx.y;
    const int t = threadIdx.x;
    const float* __restrict__ src = hm_in + (size_t)b*HH;
    float* __restrict__ agg = g_agg + (size_t)b*AW*AW;
    float* rowmax = g_rowmax + b*AW;
    int*   rowcol = g_rowcol + b*AW;
    unsigned* seen = g_seen + (size_t)b*BW;
    unsigned* dup  = g_dup  + (size_t)b*BW;

    __shared__ float V[BAND][HN];        // 42944 B

    const int r0 = s*BAND;

    // Vertical 5-sums into shared (register ring; coalesced)
    if (t < HN) {
        const int j = t;
        float a0 = src[(r0+0)*HN + j];
        float a1 = src[(r0+1)*HN + j];
        float a2 = src[(r0+2)*HN + j];
        float a3 = src[(r0+3)*HN + j];
        #pragma unroll
        for (int i = 0; i < BAND; i++) {
            float a4 = src[(r0+i+4)*HN + j];
            V[i][j] = a0 + a1 + a2 + a3 + a4;
            a0 = a1; a1 = a2; a2 = a3; a3 = a4;
        }
    }

    // Bloom build: only values > THRESH (only these are ever bloom-queried)
    {
        const int lo4 = (int)(((long long)HH4 * s)     / BAND);
        const int hi4 = (int)(((long long)HH4 * (s+1)) / BAND);
        const float4* s4 = (const float4*)src;
        for (int i = lo4 + t; i < hi4; i += 512) {
            float4 x = s4[i];
            float vals[4] = {x.x, x.y, x.z, x.w};
            #pragma unroll
            for (int e = 0; e < 4; e++) {
                float vv = vals[e];
                if (vv > THRESH) {
                    unsigned h = bhash(vv);
                    unsigned m = 1u << (h & 31);
                    unsigned old = atomicOr(&seen[h >> 5], m);
                    if (old & m) atomicOr(&dup[h >> 5], m);
                }
            }
        }
    }
    __syncthreads();

    // Horizontal 5-sums -> box mean, stored + per-row argmax (first occurrence)
    {
        const int warp = t >> 5, lane = t & 31;
        for (int il = warp; il < BAND; il += 16) {
            const int i = r0 + il;
            const float* vr = V[il];
            float best = -FLT_MAX; int bestc = 0;
            for (int cb = lane*4; cb < AW; cb += 128) {
                float4 x = *(const float4*)(vr + cb);
                float4 y = *(const float4*)(vr + cb + 4);
                float a0v = (x.x + x.y + x.z + x.w + y.x) / 25.0f;
                float a1v = (x.y + x.z + x.w + y.x + y.y) / 25.0f;
                float a2v = (x.z + x.w + y.x + y.y + y.z) / 25.0f;
                float a3v = (x.w + y.x + y.y + y.z + y.w) / 25.0f;
                agg[i*AW + cb + 0] = a0v;
                agg[i*AW + cb + 1] = a1v;
                agg[i*AW + cb + 2] = a2v;
                agg[i*AW + cb + 3] = a3v;
                if (a0v > best) { best = a0v; bestc = cb + 0; }
                if (a1v > best) { best = a1v; bestc = cb + 1; }
                if (a2v > best) { best = a2v; bestc = cb + 2; }
                if (a3v > best) { best = a3v; bestc = cb + 3; }
            }
            for (int off = 16; off > 0; off >>= 1) {
                float ov = __shfl_down_sync(0xFFFFFFFFu, best, off);
                int   oc = __shfl_down_sync(0xFFFFFFFFu, bestc, off);
                if (ov > best || (ov == best && oc < bestc)) { best = ov; bestc = oc; }
            }
            if (lane == 0) { rowmax[i] = best; rowcol[i] = bestc; }
        }
    }
}

// ---------------------------------------------------------------------------
// Kernel B: greedy peaks + mean-shift + confidences + bloom clear, fused.
// One block (768 thr) per batch. Warp0-only argmax; merged update+rescan.
// ---------------------------------------------------------------------------
__global__ __launch_bounds__(NTH) void fde_sample(const float* __restrict__ hm_in,
                                                  float* __restrict__ out) {
    const int b = blockIdx.x;
    const int t = threadIdx.x;
    const int warp = t >> 5, lane = t & 31;
    const float* __restrict__ src = hm_in + (size_t)b*HH;
    float* __restrict__ agg = g_agg + (size_t)b*AW*AW;
    unsigned* seen = g_seen + (size_t)b*BW;
    unsigned* dup  = g_dup  + (size_t)b*BW;

    __shared__ float rm[AW];
    __shared__ int   rc[AW];
    __shared__ int   wins_r[KK], wins_c[KK];
    __shared__ float cl[KK][2];
    __shared__ float part[KK][4][3];
    __shared__ int   s_r, s_c, s_need, s_scanmin;
    __shared__ float s_maxv;

    if (t < AW) { rm[t] = g_rowmax[b*AW + t]; rc[t] = g_rowcol[b*AW + t]; }
    __syncthreads();

    // ================= greedy K=6 peak extraction =================
    for (int step = 0; step < KK; step++) {
        // ---- warp 0 alone: argmax over rows + window max + bloom check ----
        if (warp == 0) {
            float v = -FLT_MAX; int id = 0x7FFFFFFF;
            for (int row = lane; row < AW; row += 32) {
                float x = rm[row];
                if (x > v) { v = x; id = row*AW + rc[row]; }   // rows ascend per lane
            }
            for (int off = 16; off > 0; off >>= 1) {
                float ov = __shfl_down_sync(0xFFFFFFFFu, v, off);
                int   oi = __shfl_down_sync(0xFFFFFFFFu, id, off);
                if (ov > v || (ov == v && oi < id)) { v = ov; id = oi; }
            }
            int id0 = __shfl_sync(0xFFFFFFFFu, id, 0);
            int r = id0 / AW, c = id0 % AW;
            // window max over virtually-zeroed src (first occurrence: min index)
            int lwr[KK], lwc[KK];
            #pragma unroll
            for (int s = 0; s < KK; s++) { lwr[s] = wins_r[s]; lwc[s] = wins_c[s]; }
            float wv = -FLT_MAX; int widx = 0x7FFFFFFF;
            if (lane < 25) {
                int ii = r + lane/5, jj = c + lane%5;
                float x = src[ii*HN + jj];
                if (in_wins_reg(ii, jj, lwr, lwc, step)) x = 0.0f;
                wv = x; widx = ii*HN + jj;
            }
            for (int off = 16; off > 0; off >>= 1) {
                float ov = __shfl_down_sync(0xFFFFFFFFu, wv, off);
                int   oi = __shfl_down_sync(0xFFFFFFFFu, widx, off);
                if (ov > wv || (ov == wv && oi < widx)) { wv = ov; widx = oi; }
            }
            if (lane == 0) {
                s_r = r; s_c = c; s_maxv = wv; s_scanmin = widx;
                wins_r[step] = r; wins_c[step] = c;      // place window now
                cl[step][0] = (float)(widx / HN);        // provisional (scan may lower)
                cl[step][1] = (float)(widx % HN);
                int need = 1;
                if (wv > THRESH) {          // bloom covers exactly values > THRESH
                    unsigned h = bhash(wv);
                    need = (dup[h >> 5] >> (h & 31)) & 1;
                }
                s_need = need;
            }
        }
        __syncthreads();
        const int   r  = s_r, c = s_c;
        const float mv = s_maxv;

        // rare: first global unmasked index with value == mv
        if (s_need) {
            int lwr[KK], lwc[KK];
            #pragma unroll
            for (int s = 0; s < KK; s++) { lwr[s] = wins_r[s]; lwc[s] = wins_c[s]; }
            const int limit = s_scanmin;
            const float4* S4 = (const float4*)src;
            const int n4 = (limit + 3) >> 2;
            for (int i4 = t; i4 < n4; i4 += NTH) {
                float4 x = S4[i4];
                if (x.x == mv || x.y == mv || x.z == mv || x.w == mv) {
                    int base = i4 << 2;
                    float vals[4] = {x.x, x.y, x.z, x.w};
                    #pragma unroll
                    for (int e = 0; e < 4; e++) {
                        int idx = base + e;
                        if (vals[e] == mv && idx < limit) {
                            int ii = idx / HN, jj = idx - ii*HN;
                            if (!in_wins_reg(ii, jj, lwr, lwc, step))   // mask EXCLUDES current
                                atomicMin(&s_scanmin, idx);
                        }
                    }
                }
            }
            __syncthreads();
            if (t == 0) {
                int fh = s_scanmin;
                cl[step][0] = (float)(fh / HN);
                cl[step][1] = (float)(fh % HN);
            }
        }

        // ---- merged: recompute changed agg cells AND rescan rows, warp per row ----
        const int ra0 = max(r-4, 0), ra1 = min(r+4, AW-1);
        const int ca0 = max(c-4, 0), ca1 = min(c+4, AW-1);
        const int nr = ra1 - ra0 + 1, nc = ca1 - ca0 + 1;
        if (warp < nr) {
            const int i = ra0 + warp;
            float newv = -FLT_MAX;
            if (lane < nc) {
                int lwr[KK], lwc[KK];
                #pragma unroll
                for (int s = 0; s < KK; s++) { lwr[s] = wins_r[s]; lwc[s] = wins_c[s]; }
                const int j = ca0 + lane;
                float V[5];
                #pragma unroll
                for (int dj = 0; dj < 5; dj++) {
                    const int jj = j + dj;
                    float v = 0.0f;
                    #pragma unroll
                    for (int di = 0; di < 5; di++) {
                        const int ii = i + di;
                        float x = src[ii*HN + jj];
                        if (in_wins_reg(ii, jj, lwr, lwc, step+1)) x = 0.0f;
                        v += x;
                    }
                    V[dj] = v;
                }
                newv = (V[0] + V[1] + V[2] + V[3] + V[4]) / 25.0f;
                agg[i*AW + j] = newv;              // for future steps
            }
            __syncwarp();
            // rescan full row, substituting the fresh values via shuffle
            const float* ar = agg + i*AW;
            float best = -FLT_MAX; int bestc = 0;
            #pragma unroll 4
            for (int itx = 0; itx < 16; itx++) {
                const int j = lane + itx*32;
                float sub = __shfl_sync(0xFFFFFFFFu, newv, (j - ca0) & 31);
                float x = (j < AW) ? ar[j] : -FLT_MAX;
                if (j >= ca0 && j <= ca1) x = sub;
                if (x > best) { best = x; bestc = j; }
            }
            for (int off = 16; off > 0; off >>= 1) {
                float ov = __shfl_down_sync(0xFFFFFFFFu, best, off);
                int   oc = __shfl_down_sync(0xFFFFFFFFu, bestc, off);
                if (ov > best || (ov == best && oc < bestc)) { best = ov; bestc = oc; }
            }
            if (lane == 0) { rm[i] = best; rc[i] = bestc; }
        }
        __syncthreads();
    }

    // ================= mean-shift (10 iters), 4 warps per cluster =================
    const int g   = t >> 7;              // cluster 0..5
    const int wg  = t & 127;
    const int wig = (t >> 5) & 3;        // warp within group
    // precompute relative pixel coords (constant across iterations)
    int ri[6], rj[6];
    #pragma unroll
    for (int p = 0; p < 6; p++) {
        int idx = wg + p*128;
        ri[p] = idx/26; rj[p] = idx%26;  // idx<676 guard applied in loop
    }
    for (int it = 0; it < NITERS; it++) {
        float cli[KK], clj[KK];
        #pragma unroll
        for (int k = 0; k < KK; k++) { cli[k] = cl[k][0]; clj[k] = cl[k][1]; }

        const int i0 = (int)floorf(cli[g]) - 12;
        const int j0 = (int)floorf(clj[g]) - 12;
        float swi = 0.0f, swj = 0.0f, sw = 0.0f;
        #pragma unroll
        for (int p = 0; p < 6; p++) {
            if (wg + p*128 >= 676) break;
            int i = i0 + ri[p], j = j0 + rj[p];
            if (i < 0 || i >= HN || j < 0 || j >= HN) continue;
            float fi = (float)i, fj = (float)j;
            float d2min = FLT_MAX, d2w = 0.0f;
            #pragma unroll
            for (int k = 0; k < KK; k++) {
                float di = fi - cli[k], dj = fj - clj[k];
                float d2 = fmaxf(di*di + dj*dj, 1e-6f);
                d2min = fminf(d2min, d2);
                if (k == g) d2w = d2;
            }
            if (d2w < 144.0f) {
                float m   = d2min * rsqrtf(d2min);
                float inv = rsqrtf(d2w);
                float wv  = src[i*HN + j] * m * inv * inv;
                swi += wv * fi; swj += wv * fj; sw += wv;
            }
        }
        for (int off = 16; off > 0; off >>= 1) {
            swi += __shfl_xor_sync(0xFFFFFFFFu, swi, off);
            swj += __shfl_xor_sync(0xFFFFFFFFu, swj, off);
            sw  += __shfl_xor_sync(0xFFFFFFFFu, sw,  off);
        }
        if (lane == 0) { part[g][wig][0] = swi; part[g][wig][1] = swj; part[g][wig][2] = sw; }
        __syncthreads();
        if (wg == 0) {
            float a = part[g][0][0]+part[g][1][0]+part[g][2][0]+part[g][3][0];
            float bsum = part[g][0][1]+part[g][1][1]+part[g][2][1]+part[g][3][1];
            float cS = part[g][0][2]+part[g][1][2]+part[g][2][2]+part[g][3][2];
            cl[g][0] = a / cS; cl[g][1] = bsum / cS;
        }
        __syncthreads();
    }

    // ================= round + clamped 4x4 confidence =================
    if (wg < 32) {
        const int ci = (int)rintf(cl[g][0]);
        const int cj = (int)rintf(cl[g][1]);
        const int si = min(max(ci - RADIUS, 0), HN - 2*RADIUS);
        const int sj = min(max(cj - RADIUS, 0), HN - 2*RADIUS);
        float conf = 0.0f;
        if (lane < 16) conf = src[(si + lane/4)*HN + (sj + lane%4)];
        for (int off = 16; off > 0; off >>= 1)
            conf += __shfl_xor_sync(0xFFFFFFFFu, conf, off);
        if (lane == 0) {
            out[(b*KK + g)*2 + 0] = (float)ci;
            out[(b*KK + g)*2 + 1] = (float)cj;
            out[NB*KK*2 + b*KK + g] = conf;
        }
    }

    // ================= clear this batch's bloom for the next replay =================
    {
        uint4 z = make_uint4(0,0,0,0);
        uint4* p1 = (uint4*)seen;
        uint4* p2 = (uint4*)dup;
        for (int i = t; i < (BW >> 2); i += NTH) { p1[i] = z; p2[i] = z; }
    }
}

extern "C" void kernel_launch(void* const* d_in, const int* in_sizes, int n_in,
                              void* d_out, int out_size) {
    const float* hm = (const float*)d_in[0];
    float* out = (float*)d_out;
    fde_build <<<dim3(NB, BAND), 512>>>(hm);
    fde_sample<<<NB, NTH>>>(hm, out);
}

// round 11
// speedup vs baseline: 1.2329x; 1.2329x over previous
#include <cuda_runtime.h>
#include <cfloat>

#define HN      488
#define HH      (HN*HN)          // 238144
#define HH4     (HH/4)           // 59536
#define AW      484              // H - RECLEN + 1
#define KK      6
#define NB      32
#define NITERS  10
#define RADIUS  2
#define BAND    22               // 22 bands x 22 rows = 484
#define BW      8192             // uint32 words per batch (2^18 bits)
#define THRESH  0.90f
#define NTH     768

// Scratch (device globals: zero-initialized; bloom cleared by sample's tail)
__device__ float    g_agg[NB*AW*AW];     // 5x5 box means, 30MB (L2-resident)
__device__ float    g_rowmax[NB*AW];
__device__ int      g_rowcol[NB*AW];
__device__ unsigned g_seen[NB*BW];
__device__ unsigned g_dup [NB*BW];

__device__ __forceinline__ unsigned bhash(float v) {
    return (__float_as_uint(v) * 2654435761u) >> 14;   // 18-bit hash
}

// Windows held in registers (fully unrolled; wr/wc stay in regs)
__device__ __forceinline__ bool in_wins_reg(int ii, int jj,
                                            const int (&wr)[KK], const int (&wc)[KK], int nw) {
    bool hit = false;
    #pragma unroll
    for (int s = 0; s < KK; s++)
        if (s < nw && ii >= wr[s] && ii < wr[s]+5 && jj >= wc[s] && jj < wc[s]+5) hit = true;
    return hit;
}

// ---------------------------------------------------------------------------
// Kernel A: box-mean map (stored) + per-row argmax + thresholded dup bloom.
// grid (32 batches, 22 bands), 512 threads.
// ---------------------------------------------------------------------------
__global__ __launch_bounds__(512) void fde_build(const float* __restrict__ hm_in) {
    const int b = blockIdx.x, s = blockIdx.y;
    const int t = threadIdx.x;
    const float* __restrict__ src = hm_in + (size_t)b*HH;
    float* __restrict__ agg = g_agg + (size_t)b*AW*AW;
    float* rowmax = g_rowmax + b*AW;
    int*   rowcol = g_rowcol + b*AW;
    unsigned* seen = g_seen + (size_t)b*BW;
    unsigned* dup  = g_dup  + (size_t)b*BW;

    __shared__ float V[BAND][HN];        // 42944 B

    const int r0 = s*BAND;

    // Vertical 5-sums into shared (register ring; coalesced)
    if (t < HN) {
        const int j = t;
        float a0 = src[(r0+0)*HN + j];
        float a1 = src[(r0+1)*HN + j];
        float a2 = src[(r0+2)*HN + j];
        float a3 = src[(r0+3)*HN + j];
        #pragma unroll
        for (int i = 0; i < BAND; i++) {
            float a4 = src[(r0+i+4)*HN + j];
            V[i][j] = a0 + a1 + a2 + a3 + a4;
            a0 = a1; a1 = a2; a2 = a3; a3 = a4;
        }
    }

    // Bloom build: only values > THRESH (only these are ever bloom-queried)
    {
        const int lo4 = (int)(((long long)HH4 * s)     / BAND);
        const int hi4 = (int)(((long long)HH4 * (s+1)) / BAND);
        const float4* s4 = (const float4*)src;
        for (int i = lo4 + t; i < hi4; i += 512) {
            float4 x = s4[i];
            float vals[4] = {x.x, x.y, x.z, x.w};
            #pragma unroll
            for (int e = 0; e < 4; e++) {
                float vv = vals[e];
                if (vv > THRESH) {
                    unsigned h = bhash(vv);
                    unsigned m = 1u << (h & 31);
                    unsigned old = atomicOr(&seen[h >> 5], m);
                    if (old & m) atomicOr(&dup[h >> 5], m);
                }
            }
        }
    }
    __syncthreads();

    // Horizontal 5-sums -> box mean, stored + per-row argmax (first occurrence)
    {
        const int warp = t >> 5, lane = t & 31;
        for (int il = warp; il < BAND; il += 16) {
            const int i = r0 + il;
            const float* vr = V[il];
            float best = -FLT_MAX; int bestc = 0;
            for (int cb = lane*4; cb < AW; cb += 128) {
                float4 x = *(const float4*)(vr + cb);
                float4 y = *(const float4*)(vr + cb + 4);
                float a0v = (x.x + x.y + x.z + x.w + y.x) / 25.0f;
                float a1v = (x.y + x.z + x.w + y.x + y.y) / 25.0f;
                float a2v = (x.z + x.w + y.x + y.y + y.z) / 25.0f;
                float a3v = (x.w + y.x + y.y + y.z + y.w) / 25.0f;
                agg[i*AW + cb + 0] = a0v;
                agg[i*AW + cb + 1] = a1v;
                agg[i*AW + cb + 2] = a2v;
                agg[i*AW + cb + 3] = a3v;
                if (a0v > best) { best = a0v; bestc = cb + 0; }
                if (a1v > best) { best = a1v; bestc = cb + 1; }
                if (a2v > best) { best = a2v; bestc = cb + 2; }
                if (a3v > best) { best = a3v; bestc = cb + 3; }
            }
            for (int off = 16; off > 0; off >>= 1) {
                float ov = __shfl_down_sync(0xFFFFFFFFu, best, off);
                int   oc = __shfl_down_sync(0xFFFFFFFFu, bestc, off);
                if (ov > best || (ov == best && oc < bestc)) { best = ov; bestc = oc; }
            }
            if (lane == 0) { rowmax[i] = best; rowcol[i] = bestc; }
        }
    }
}

// ---------------------------------------------------------------------------
// Kernel B: greedy peaks + mean-shift + confidences + bloom clear, fused.
// One block (768 thr) per batch. Incremental agg updates; windows in regs.
// ---------------------------------------------------------------------------
__global__ __launch_bounds__(NTH) void fde_sample(const float* __restrict__ hm_in,
                                                  float* __restrict__ out) {
    const int b = blockIdx.x;
    const int t = threadIdx.x;
    const int warp = t >> 5, lane = t & 31;
    const float* __restrict__ src = hm_in + (size_t)b*HH;
    float* __restrict__ agg = g_agg + (size_t)b*AW*AW;
    unsigned* seen = g_seen + (size_t)b*BW;
    unsigned* dup  = g_dup  + (size_t)b*BW;

    __shared__ float rm[AW];
    __shared__ int   rc[AW];
    __shared__ float swv[32];
    __shared__ int   sid[32];
    __shared__ int   wins_r[KK], wins_c[KK];
    __shared__ float cl[KK][2];
    __shared__ float part[KK][4][3];
    __shared__ int   s_r, s_c, s_need, s_scanmin;
    __shared__ float s_maxv;

    if (t < AW) { rm[t] = g_rowmax[b*AW + t]; rc[t] = g_rowcol[b*AW + t]; }
    if (warp >= 16 && lane == 0 && warp < 32) { swv[warp] = -FLT_MAX; sid[warp] = 0x7FFFFFFF; }
    __syncthreads();

    // ================= greedy K=6 peak extraction =================
    for (int step = 0; step < KK; step++) {
        // global argmax over per-row maxima (tie -> smallest flat idx)
        {
            float v = -FLT_MAX; int id = 0x7FFFFFFF;
            if (t < AW) { v = rm[t]; id = t*AW + rc[t]; }
            for (int off = 16; off > 0; off >>= 1) {
                float ov = __shfl_down_sync(0xFFFFFFFFu, v, off);
                int   oi = __shfl_down_sync(0xFFFFFFFFu, id, off);
                if (ov > v || (ov == v && oi < id)) { v = ov; id = oi; }
            }
            if (lane == 0 && warp < 16) { swv[warp] = v; sid[warp] = id; }
        }
        __syncthreads();
        if (warp == 0) {
            float v = (lane < 16) ? swv[lane] : -FLT_MAX;
            int  id = (lane < 16) ? sid[lane] : 0x7FFFFFFF;
            for (int off = 8; off > 0; off >>= 1) {
                float ov = __shfl_down_sync(0xFFFFFFFFu, v, off);
                int   oi = __shfl_down_sync(0xFFFFFFFFu, id, off);
                if (ov > v || (ov == v && oi < id)) { v = ov; id = oi; }
            }
            int id0 = __shfl_sync(0xFFFFFFFFu, id, 0);
            int r = id0 / AW, c = id0 % AW;
            // window max over virtually-zeroed src (first occurrence: min index)
            int lwr[KK], lwc[KK];
            #pragma unroll
            for (int s = 0; s < KK; s++) { lwr[s] = wins_r[s]; lwc[s] = wins_c[s]; }
            float wv = -FLT_MAX; int widx = 0x7FFFFFFF;
            if (lane < 25) {
                int ii = r + lane/5, jj = c + lane%5;
                float x = src[ii*HN + jj];
                if (in_wins_reg(ii, jj, lwr, lwc, step)) x = 0.0f;
                wv = x; widx = ii*HN + jj;
            }
            for (int off = 16; off > 0; off >>= 1) {
                float ov = __shfl_down_sync(0xFFFFFFFFu, wv, off);
                int   oi = __shfl_down_sync(0xFFFFFFFFu, widx, off);
                if (ov > wv || (ov == wv && oi < widx)) { wv = ov; widx = oi; }
            }
            if (lane == 0) {
                s_r = r; s_c = c; s_maxv = wv; s_scanmin = widx;
                int need = 1;
                if (wv > THRESH) {          // bloom covers exactly values > THRESH
                    unsigned h = bhash(wv);
                    need = (dup[h >> 5] >> (h & 31)) & 1;
                }
                s_need = need;
            }
        }
        __syncthreads();
        const int   r  = s_r, c = s_c;
        const float mv = s_maxv;

        // rare: first global unmasked index with value == mv
        if (s_need) {
            int lwr[KK], lwc[KK];
            #pragma unroll
            for (int s = 0; s < KK; s++) { lwr[s] = wins_r[s]; lwc[s] = wins_c[s]; }
            const int limit = s_scanmin;
            const float4* S4 = (const float4*)src;
            const int n4 = (limit + 3) >> 2;
            for (int i4 = t; i4 < n4; i4 += NTH) {
                float4 x = S4[i4];
                if (x.x == mv || x.y == mv || x.z == mv || x.w == mv) {
                    int base = i4 << 2;
                    float vals[4] = {x.x, x.y, x.z, x.w};
                    #pragma unroll
                    for (int e = 0; e < 4; e++) {
                        int idx = base + e;
                        if (vals[e] == mv && idx < limit) {
                            int ii = idx / HN, jj = idx - ii*HN;
                            if (!in_wins_reg(ii, jj, lwr, lwc, step))
                                atomicMin(&s_scanmin, idx);
                        }
                    }
                }
            }
            __syncthreads();
        }
        if (t == 0) {
            int fh = s_scanmin;
            cl[step][0] = (float)(fh / HN);
            cl[step][1] = (float)(fh % HN);
            wins_r[step] = r; wins_c[step] = c;     // place window
        }
        __syncthreads();

        // recompute ONLY the <=81 changed agg cells from masked src
        const int ra0 = max(r-4, 0), ra1 = min(r+4, AW-1);
        const int ca0 = max(c-4, 0), ca1 = min(c+4, AW-1);
        const int nr = ra1 - ra0 + 1, nc = ca1 - ca0 + 1;
        if (t < nr*nc) {
            int lwr[KK], lwc[KK];
            #pragma unroll
            for (int s = 0; s < KK; s++) { lwr[s] = wins_r[s]; lwc[s] = wins_c[s]; }
            const int i = ra0 + t/nc, j = ca0 + t%nc;
            float V[5];
            #pragma unroll
            for (int dj = 0; dj < 5; dj++) {
                const int jj = j + dj;
                float v = 0.0f;
                #pragma unroll
                for (int di = 0; di < 5; di++) {
                    const int ii = i + di;
                    float x = src[ii*HN + jj];
                    if (in_wins_reg(ii, jj, lwr, lwc, step+1)) x = 0.0f;
                    v += x;
                }
                V[dj] = v;
            }
            agg[i*AW + j] = (V[0] + V[1] + V[2] + V[3] + V[4]) / 25.0f;
        }
        __syncthreads();

        // rescan the <=9 affected rows from stored agg (warp per row)
        if (warp < nr) {
            const int i = ra0 + warp;
            const float* ar = agg + i*AW;
            float best = -FLT_MAX; int bestc = 0;
            for (int j = lane; j < AW; j += 32) {
                float x = ar[j];
                if (x > best) { best = x; bestc = j; }
            }
            for (int off = 16; off > 0; off >>= 1) {
                float ov = __shfl_down_sync(0xFFFFFFFFu, best, off);
                int   oc = __shfl_down_sync(0xFFFFFFFFu, bestc, off);
                if (ov > best || (ov == best && oc < bestc)) { best = ov; bestc = oc; }
            }
            if (lane == 0) { rm[i] = best; rc[i] = bestc; }
        }
        __syncthreads();
    }

    // ================= mean-shift (10 iters), 4 warps per cluster =================
    const int g   = t >> 7;              // cluster 0..5
    const int wg  = t & 127;
    const int wig = (t >> 5) & 3;        // warp within group
    for (int it = 0; it < NITERS; it++) {
        float cli[KK], clj[KK];
        #pragma unroll
        for (int k = 0; k < KK; k++) { cli[k] = cl[k][0]; clj[k] = cl[k][1]; }

        const int i0 = (int)floorf(cli[g]) - 12;
        const int j0 = (int)floorf(clj[g]) - 12;
        float swi = 0.0f, swj = 0.0f, sw = 0.0f;
        for (int idx = wg; idx < 26*26; idx += 128) {
            int i = i0 + idx/26, j = j0 + idx%26;
            if (i < 0 || i >= HN || j < 0 || j >= HN) continue;
            float fi = (float)i, fj = (float)j;
            // clamp hoisted: min_k max(d2_k,c) == max(min_k d2_k, c)  (exact)
            float d2min = FLT_MAX, d2w = 0.0f;
            #pragma unroll
            for (int k = 0; k < KK; k++) {
                float di = fi - cli[k], dj = fj - clj[k];
                float d2 = di*di + dj*dj;
                d2min = fminf(d2min, d2);
                if (k == g) d2w = d2;
            }
            d2min = fmaxf(d2min, 1e-6f);
            d2w   = fmaxf(d2w,   1e-6f);
            if (d2w < 144.0f) {
                float m   = d2min * rsqrtf(d2min);
                float inv = rsqrtf(d2w);
                float wv  = src[i*HN + j] * m * inv * inv;
                swi += wv * fi; swj += wv * fj; sw += wv;
            }
        }
        for (int off = 16; off > 0; off >>= 1) {
            swi += __shfl_xor_sync(0xFFFFFFFFu, swi, off);
            swj += __shfl_xor_sync(0xFFFFFFFFu, swj, off);
            sw  += __shfl_xor_sync(0xFFFFFFFFu, sw,  off);
        }
        if (lane == 0) { part[g][wig][0] = swi; part[g][wig][1] = swj; part[g][wig][2] = sw; }
        __syncthreads();
        if (wg == 0) {
            float a = part[g][0][0]+part[g][1][0]+part[g][2][0]+part[g][3][0];
            float bsum = part[g][0][1]+part[g][1][1]+part[g][2][1]+part[g][3][1];
            float cS = part[g][0][2]+part[g][1][2]+part[g][2][2]+part[g][3][2];
            cl[g][0] = a / cS; cl[g][1] = bsum / cS;
        }
        __syncthreads();
    }

    // ================= round + clamped 4x4 confidence =================
    if (wg < 32) {
        const int ci = (int)rintf(cl[g][0]);
        const int cj = (int)rintf(cl[g][1]);
        const int si = min(max(ci - RADIUS, 0), HN - 2*RADIUS);
        const int sj = min(max(cj - RADIUS, 0), HN - 2*RADIUS);
        float conf = 0.0f;
        if (lane < 16) conf = src[(si + lane/4)*HN + (sj + lane%4)];
        for (int off = 16; off > 0; off >>= 1)
            conf += __shfl_xor_sync(0xFFFFFFFFu, conf, off);
        if (lane == 0) {
            out[(b*KK + g)*2 + 0] = (float)ci;
            out[(b*KK + g)*2 + 1] = (float)cj;
            out[NB*KK*2 + b*KK + g] = conf;
        }
    }

    // ================= clear this batch's bloom for the next replay =================
    {
        uint4 z = make_uint4(0,0,0,0);
        uint4* p1 = (uint4*)seen;
        uint4* p2 = (uint4*)dup;
        for (int i = t; i < (BW >> 2); i += NTH) { p1[i] = z; p2[i] = z; }
    }
}

extern "C" void kernel_launch(void* const* d_in, const int* in_sizes, int n_in,
                              void* d_out, int out_size) {
    const float* hm = (const float*)d_in[0];
    float* out = (float*)d_out;
    fde_build <<<dim3(NB, BAND), 512>>>(hm);
    fde_sample<<<NB, NTH>>>(hm, out);
}